// round 6
// baseline (speedup 1.0000x reference)
#include <cuda_runtime.h>
#include <cuda_bf16.h>
#include <cstdint>
#include <cstddef>

#define N_NODES 50000
#define N_EDGES 500000
#define HID 128
#define NREL 4
#define BN_EPS 1e-5f
#define NBLK 49            // ceil(50000/1024)
#define MPAD 50048         // 391 * 128

#if defined(__CUDA_ARCH_FEAT_SM103_ALL)
#define HAS_TCGEN05 1
#else
#define HAS_TCGEN05 0
#endif

// ---------------- PTX helpers -------------------------------------------------
__device__ __forceinline__ uint32_t smem_to_u32(const void* p) {
    uint32_t a;
    asm("{ .reg .u64 t; cvta.to.shared.u64 t, %1; cvt.u32.u64 %0, t; }" : "=r"(a) : "l"(p));
    return a;
}
__device__ __forceinline__ uint32_t elect_one_pred() {
    uint32_t pred;
    asm volatile("{\n\t.reg .pred p;\n\telect.sync _|p, 0xFFFFFFFF;\n\tselp.b32 %0, 1, 0, p;\n\t}" : "=r"(pred));
    return pred;
}
#define MBARRIER_INIT(mbar, count) \
    asm volatile("mbarrier.init.shared.b64 [%0], %1;" :: "r"((uint32_t)(mbar)), "r"((uint32_t)(count)) : "memory")
#define MBARRIER_INVAL(mbar) \
    asm volatile("mbarrier.inval.shared.b64 [%0];" :: "r"((uint32_t)(mbar)) : "memory")
#define MBARRIER_WAIT_PARITY(mbar, parity) do { \
    uint32_t _m = (uint32_t)(mbar); uint32_t _p = (uint32_t)(parity); uint32_t _d; \
    asm volatile("{\n\t.reg .pred p;\n\tmbarrier.try_wait.parity.acquire.cta.shared::cta.b64 p, [%1], %2;\n\tselp.b32 %0, 1, 0, p;\n\t}" \
        : "=r"(_d) : "r"(_m), "r"(_p) : "memory"); \
    if (!_d) { \
        asm volatile("{\n\t.reg .pred P1;\n\tWL_%=:\n\tmbarrier.try_wait.parity.acquire.cta.shared::cta.b64 P1, [%0], %1, 0x989680;\n\t@P1 bra.uni WD_%=;\n\tbra.uni WL_%=;\n\tWD_%=:\n\t}" \
            :: "r"(_m), "r"(_p) : "memory"); \
    } \
} while (0)

#if HAS_TCGEN05
#define TCGEN05_ALLOC(smem_addr, nCols) \
    asm volatile("tcgen05.alloc.cta_group::1.sync.aligned.shared::cta.b32 [%0], %1;" \
        :: "r"((uint32_t)(smem_addr)), "r"((uint32_t)(nCols)) : "memory")
#define TCGEN05_DEALLOC(tmem, nCols) \
    asm volatile("tcgen05.dealloc.cta_group::1.sync.aligned.b32 %0, %1;" :: "r"(tmem), "r"((uint32_t)(nCols)))
#define TCGEN05_COMMIT(mbar) \
    asm volatile("tcgen05.commit.cta_group::1.mbarrier::arrive::one.shared::cluster.b64 [%0];" \
        :: "r"((uint32_t)(mbar)) : "memory")
#define TCGEN05_FENCE_AFTER() asm volatile("tcgen05.fence::after_thread_sync;" ::: "memory")
#define TCGEN05_WAIT_LD() asm volatile("tcgen05.wait::ld.sync.aligned;" ::: "memory")
#define TCGEN05_LD_X32(r, addr) \
    asm volatile("tcgen05.ld.sync.aligned.32x32b.x32.b32 " \
        "{%0, %1, %2, %3, %4, %5, %6, %7, %8, %9, %10, %11, %12, %13, %14, %15, " \
        "%16, %17, %18, %19, %20, %21, %22, %23, %24, %25, %26, %27, %28, %29, %30, %31}, [%32];" \
        : "=r"((r)[0]), "=r"((r)[1]), "=r"((r)[2]), "=r"((r)[3]), "=r"((r)[4]), "=r"((r)[5]), "=r"((r)[6]), "=r"((r)[7]), \
          "=r"((r)[8]), "=r"((r)[9]), "=r"((r)[10]), "=r"((r)[11]), "=r"((r)[12]), "=r"((r)[13]), "=r"((r)[14]), "=r"((r)[15]), \
          "=r"((r)[16]), "=r"((r)[17]), "=r"((r)[18]), "=r"((r)[19]), "=r"((r)[20]), "=r"((r)[21]), "=r"((r)[22]), "=r"((r)[23]), \
          "=r"((r)[24]), "=r"((r)[25]), "=r"((r)[26]), "=r"((r)[27]), "=r"((r)[28]), "=r"((r)[29]), "=r"((r)[30]), "=r"((r)[31]) \
        : "r"(addr))
__device__ __forceinline__ void mma_f16_ss(uint32_t d, uint64_t adesc, uint64_t bdesc,
                                           uint32_t idesc, uint32_t en) {
    asm volatile(
        "{\n\t.reg .pred p;\n\tsetp.ne.u32 p, %5, 0;\n\t"
        "tcgen05.mma.cta_group::1.kind::f16 [%0], %1, %2, %3, {%4, %4, %4, %4}, p;\n\t}"
        :: "r"(d), "l"(adesc), "l"(bdesc), "r"(idesc), "r"(0u), "r"(en) : "memory");
}
#else
#define TCGEN05_ALLOC(smem_addr, nCols)  do {} while (0)
#define TCGEN05_DEALLOC(tmem, nCols)     do {} while (0)
#define TCGEN05_COMMIT(mbar)             do {} while (0)
#define TCGEN05_FENCE_AFTER()            do {} while (0)
#define TCGEN05_WAIT_LD()                do {} while (0)
#define TCGEN05_LD_X32(r, addr) \
    do { _Pragma("unroll") for (int _i = 0; _i < 32; ++_i) (r)[_i] = 0u; (void)(addr); } while (0)
__device__ __forceinline__ void mma_f16_ss(uint32_t, uint64_t, uint64_t, uint32_t, uint32_t) {}
#endif

#define FENCE_PROXY_ASYNC() asm volatile("fence.proxy.async.shared::cta;" ::: "memory")

// desc: SW128, version=1, SBO=64, LBO=1 (K-major)
__device__ __forceinline__ uint64_t make_desc(uint32_t addr) {
    uint64_t d = (uint64_t(2) << 61) | (uint64_t(1) << 46) | (uint64_t(64) << 32) | (uint64_t(1) << 16);
    return d | ((uint64_t)(addr >> 4) & 0x3FFF);
}
// idesc: F32 acc, BF16xBF16, M=128, N=128
#define MMA_IDESC 0x8200490u

__device__ __forceinline__ unsigned bf16_us(__nv_bfloat16 h) { return (unsigned)__bfloat16_as_ushort(h); }

// ---------------- scratch -----------------------------------------------------
__device__ int   g_cnt[NREL * N_NODES];
__device__ int   g_cursor[NREL * N_NODES];
__device__ float g_dinv[NREL * N_NODES];
__device__ int   g_rowptr[NREL * (N_NODES + 1)];
__device__ int   g_col[NREL * N_EDGES];
__device__ int   g_bsum[NREL * 64];
__device__ int   g_boff[NREL * 64];
__device__ __nv_bfloat16 g_B1hi[NREL * HID * HID];
__device__ __nv_bfloat16 g_B1lo[NREL * HID * HID];
__device__ __nv_bfloat16 g_B2hi[NREL * HID * HID];
__device__ __nv_bfloat16 g_B2lo[NREL * HID * HID];
__device__ __nv_bfloat16 g_Wphi[HID * HID];
__device__ __nv_bfloat16 g_Wplo[HID * HID];
__device__ __nv_bfloat16 g_h2hi[(size_t)MPAD * HID];
__device__ __nv_bfloat16 g_h2lo[(size_t)MPAD * HID];
__device__ float g_h1[(size_t)N_NODES * HID];
__device__ float g_bnsum[HID];
__device__ float g_bnsq[HID];
__device__ float g_bp[HID];

// ---------------- CSR build ---------------------------------------------------
__global__ void count_kernel(const int* __restrict__ ei) {
    int r = blockIdx.y;
    int e = blockIdx.x * blockDim.x + threadIdx.x;
    if (e >= N_EDGES) return;
    int dst = ei[((size_t)r * 2 + 1) * N_EDGES + e];
    atomicAdd(&g_cnt[r * N_NODES + dst], 1);
}

__global__ void scanA_kernel() {
    int r = blockIdx.y, blk = blockIdx.x, tid = threadIdx.x;
    __shared__ int s[1024];
    int i = blk * 1024 + tid;
    int v0 = (i < N_NODES) ? g_cnt[r * N_NODES + i] : 0;
    s[tid] = v0;
    #pragma unroll
    for (int d = 1; d < 1024; d <<= 1) {
        __syncthreads();
        int t = (tid >= d) ? s[tid - d] : 0;
        __syncthreads();
        s[tid] += t;
    }
    __syncthreads();
    if (i < N_NODES) {
        g_rowptr[r * (N_NODES + 1) + i + 1] = s[tid];
        g_dinv[r * N_NODES + i] = rsqrtf((float)v0 + 1.0f);
    }
    if (tid == 1023) g_bsum[r * 64 + blk] = s[tid];
}

__global__ void scanB_kernel() {
    int r = blockIdx.x, t = threadIdx.x;
    __shared__ int s[64];
    int v = (t < NBLK) ? g_bsum[r * 64 + t] : 0;
    s[t] = v;
    __syncthreads();
    #pragma unroll
    for (int d = 1; d < 64; d <<= 1) {
        int x = (t >= d) ? s[t - d] : 0;
        __syncthreads();
        s[t] += x;
        __syncthreads();
    }
    g_boff[r * 64 + t] = s[t] - v;
    if (t == 0) g_rowptr[r * (N_NODES + 1)] = 0;
}

__global__ void scanC_kernel() {
    int r = blockIdx.y;
    int i = blockIdx.x * 1024 + threadIdx.x;
    if (i < N_NODES)
        g_rowptr[r * (N_NODES + 1) + i + 1] += g_boff[r * 64 + blockIdx.x];
}

__global__ void fill_kernel(const int* __restrict__ ei) {
    int r = blockIdx.y;
    int e = blockIdx.x * blockDim.x + threadIdx.x;
    if (e >= N_EDGES) return;
    int src = ei[(size_t)r * 2 * N_EDGES + e];
    int dst = ei[((size_t)r * 2 + 1) * N_EDGES + e];
    int pos = g_rowptr[r * (N_NODES + 1) + dst] + atomicAdd(&g_cursor[r * N_NODES + dst], 1);
    g_col[(size_t)r * N_EDGES + pos] = src;
}

// ---------------- weight prep --------------------------------------------------
__global__ void bprep_kernel(const float* __restrict__ W1, const float* __restrict__ W2) {
    int i = blockIdx.x * blockDim.x + threadIdx.x;
    if (i >= NREL * HID * HID) return;
    int r = i >> 14, rem = i & 16383;
    int n = rem >> 7, k = rem & 127;
    size_t src = (size_t)r * 16384 + k * 128 + n;
    size_t dst = (size_t)r * 16384 + n * 128 + k;
    float v1 = W1[src];
    __nv_bfloat16 h1 = __float2bfloat16_rn(v1);
    g_B1hi[dst] = h1;
    g_B1lo[dst] = __float2bfloat16_rn(v1 - __bfloat162float(h1));
    float v2 = W2[src];
    __nv_bfloat16 h2 = __float2bfloat16_rn(v2);
    g_B2hi[dst] = h2;
    g_B2lo[dst] = __float2bfloat16_rn(v2 - __bfloat162float(h2));
}

// ---------------- fused aggregate + tcgen05 split-bf16 GEMM --------------------
// Block handles 128 nodes. For each relation: 8 warps gather+aggregate 16 nodes
// each from X (via CSR), split to bf16 hi/lo, write straight into swizzled SMEM
// A tiles; load B(r) hi/lo; issue 3x8 MMAs accumulating into TMEM.
// modes:
//   0: Hout = relu(D)  (fp32, feeds the next layer's gather)
//   1: H2hi/H2lo = split(relu(D)); fused BN column stats
#define SM_AHI 1024
#define SM_ALO (1024 + 32768)
#define SM_BHI (1024 + 65536)
#define SM_BLO (1024 + 98304)
#define SM_TOTAL (1024 + 131072)
#define SM_MBAR 8
#define SM_BIAS 16

__global__ void __launch_bounds__(256) fused_agg_gemm(
    const float* __restrict__ X,
    const __nv_bfloat16* __restrict__ Bhi, const __nv_bfloat16* __restrict__ Blo,
    const float* __restrict__ bias,
    float* __restrict__ Hout,
    __nv_bfloat16* __restrict__ H2hi, __nv_bfloat16* __restrict__ H2lo,
    int mode)
{
    extern __shared__ char sm[];
    uint32_t smb = smem_to_u32(sm);
    int tid = threadIdx.x;
    int wid = tid >> 5;
    int lane = tid & 31;
    int rowBase = blockIdx.x * 128;

    if (wid == 0) TCGEN05_ALLOC(smb, 128);
    if (tid == 0) MBARRIER_INIT(smb + SM_MBAR, 1);
    if (tid < 128) {
        float s = 0.f;
        for (int r = 0; r < NREL; r++) s += bias[r * 128 + tid];
        *(float*)(sm + SM_BIAS + tid * 4) = s;
    }
    __syncthreads();
    uint32_t tmem;
    asm volatile("ld.shared.b32 %0, [%1];" : "=r"(tmem) : "r"(smb));

    const float4* x4 = (const float4*)X;
    // lane -> smem A position: 8 bytes at swizzled(chunk=lane>>1) + (lane&1)*8
    int chunkc = lane >> 1;
    uint32_t laneHalf = (lane & 1) * 8;

    for (int r = 0; r < NREL; ++r) {
        if (r) {
            MBARRIER_WAIT_PARITY(smb + SM_MBAR, (r - 1) & 1);
            __syncthreads();
        }
        const float* dinv = g_dinv + r * N_NODES;
        const int* rp = g_rowptr + r * (N_NODES + 1);
        const int* col = g_col + (size_t)r * N_EDGES;

        // ---- gather-aggregate 16 nodes per warp, write swizzled bf16 hi/lo ----
        #pragma unroll 1
        for (int i = 0; i < 16; ++i) {
            int row = wid * 16 + i;          // 0..127
            int node = rowBase + row;
            float4 acc = make_float4(0.f, 0.f, 0.f, 0.f);
            if (node < N_NODES) {
                float dd = dinv[node];
                float4 xv = x4[(size_t)node * 32 + lane];
                acc.x = dd * xv.x; acc.y = dd * xv.y; acc.z = dd * xv.z; acc.w = dd * xv.w;
                int beg = rp[node];
                int end = rp[node + 1];
                int j = beg;
                for (; j + 4 <= end; j += 4) {
                    int s0 = col[j], s1 = col[j + 1], s2 = col[j + 2], s3 = col[j + 3];
                    float w0 = dinv[s0], w1 = dinv[s1], w2 = dinv[s2], w3 = dinv[s3];
                    float4 v0 = x4[(size_t)s0 * 32 + lane];
                    float4 v1 = x4[(size_t)s1 * 32 + lane];
                    float4 v2 = x4[(size_t)s2 * 32 + lane];
                    float4 v3 = x4[(size_t)s3 * 32 + lane];
                    acc.x += w0 * v0.x + w1 * v1.x + w2 * v2.x + w3 * v3.x;
                    acc.y += w0 * v0.y + w1 * v1.y + w2 * v2.y + w3 * v3.y;
                    acc.z += w0 * v0.z + w1 * v1.z + w2 * v2.z + w3 * v3.z;
                    acc.w += w0 * v0.w + w1 * v1.w + w2 * v2.w + w3 * v3.w;
                }
                for (; j < end; ++j) {
                    int s0 = col[j];
                    float w0 = dinv[s0];
                    float4 v0 = x4[(size_t)s0 * 32 + lane];
                    acc.x += w0 * v0.x; acc.y += w0 * v0.y;
                    acc.z += w0 * v0.z; acc.w += w0 * v0.w;
                }
                acc.x *= dd; acc.y *= dd; acc.z *= dd; acc.w *= dd;
            }
            float v[4] = { acc.x, acc.y, acc.z, acc.w };
            unsigned hh[2], ll[2];
            #pragma unroll
            for (int p = 0; p < 2; p++) {
                __nv_bfloat16 h0 = __float2bfloat16_rn(v[2 * p]);
                __nv_bfloat16 h1 = __float2bfloat16_rn(v[2 * p + 1]);
                __nv_bfloat16 l0 = __float2bfloat16_rn(v[2 * p] - __bfloat162float(h0));
                __nv_bfloat16 l1 = __float2bfloat16_rn(v[2 * p + 1] - __bfloat162float(h1));
                hh[p] = bf16_us(h0) | (bf16_us(h1) << 16);
                ll[p] = bf16_us(l0) | (bf16_us(l1) << 16);
            }
            uint32_t soff = (uint32_t)(((row >> 3) + ((chunkc >> 3) << 4)) * 1024
                                       + (row & 7) * 128 + (chunkc & 7) * 16);
            soff = (soff ^ ((soff >> 3) & 0x70)) + laneHalf;
            *(uint2*)(sm + SM_AHI + soff) = make_uint2(hh[0], hh[1]);
            *(uint2*)(sm + SM_ALO + soff) = make_uint2(ll[0], ll[1]);
        }

        // ---- load B(r) hi/lo into swizzled smem ----
        for (int c = tid; c < 2048; c += 256) {
            int row = c >> 4;
            int kc  = c & 15;
            uint32_t soff = (uint32_t)(((row >> 3) + ((kc >> 3) << 4)) * 1024 + (row & 7) * 128 + (kc & 7) * 16);
            soff = soff ^ ((soff >> 3) & 0x70);
            size_t gB = ((size_t)r * 128 + row) * 128 + kc * 8;
            *(uint4*)(sm + SM_BHI + soff) = *(const uint4*)(Bhi + gB);
            *(uint4*)(sm + SM_BLO + soff) = *(const uint4*)(Blo + gB);
        }
        __syncthreads();

        if (wid == 0) {
            FENCE_PROXY_ASYNC();
            if (elect_one_pred()) {
                uint64_t aH = make_desc(smb + SM_AHI);
                uint64_t aL = make_desc(smb + SM_ALO);
                uint64_t bH = make_desc(smb + SM_BHI);
                uint64_t bL = make_desc(smb + SM_BLO);
                #pragma unroll
                for (int s = 0; s < 8; ++s) {
                    uint64_t off = (uint64_t)((s >> 2) * 1024 + (s & 3) * 2);
                    mma_f16_ss(tmem, aH + off, bH + off, MMA_IDESC, !(r == 0 && s == 0));
                    mma_f16_ss(tmem, aH + off, bL + off, MMA_IDESC, 1u);
                    mma_f16_ss(tmem, aL + off, bH + off, MMA_IDESC, 1u);
                }
                TCGEN05_COMMIT(smb + SM_MBAR);
            }
        }
    }

    MBARRIER_WAIT_PARITY(smb + SM_MBAR, (NREL - 1) & 1);
    TCGEN05_FENCE_AFTER();

    float* vs = (float*)(sm + SM_AHI);   // [128][129] BN-stat scratch (mode 1)

    if (tid < 128) {
        int row = rowBase + tid;
        bool active = row < N_NODES;
        for (int ch = 0; ch < 4; ++ch) {
            uint32_t regs[32];
            TCGEN05_LD_X32(regs, tmem + ch * 32);
            TCGEN05_WAIT_LD();
            float v[32];
            #pragma unroll
            for (int c = 0; c < 32; ++c) {
                float b = *(const float*)(sm + SM_BIAS + (ch * 32 + c) * 4);
                v[c] = active ? fmaxf(__uint_as_float(regs[c]) + b, 0.f) : 0.f;
            }
            if (mode == 0) {
                if (active) {
                    #pragma unroll
                    for (int g = 0; g < 8; ++g)
                        *(float4*)(Hout + (size_t)row * 128 + ch * 32 + g * 4) =
                            make_float4(v[g * 4], v[g * 4 + 1], v[g * 4 + 2], v[g * 4 + 3]);
                }
            } else {
                #pragma unroll
                for (int c = 0; c < 32; ++c) vs[tid * 129 + ch * 32 + c] = v[c];
                if (active) {
                    unsigned hh[16], ll[16];
                    #pragma unroll
                    for (int p = 0; p < 16; ++p) {
                        __nv_bfloat16 h0 = __float2bfloat16_rn(v[2 * p]);
                        __nv_bfloat16 h1 = __float2bfloat16_rn(v[2 * p + 1]);
                        __nv_bfloat16 l0 = __float2bfloat16_rn(v[2 * p] - __bfloat162float(h0));
                        __nv_bfloat16 l1 = __float2bfloat16_rn(v[2 * p + 1] - __bfloat162float(h1));
                        hh[p] = bf16_us(h0) | (bf16_us(h1) << 16);
                        ll[p] = bf16_us(l0) | (bf16_us(l1) << 16);
                    }
                    #pragma unroll
                    for (int g = 0; g < 4; ++g) {
                        *(uint4*)(H2hi + (size_t)row * 128 + ch * 32 + g * 8) =
                            make_uint4(hh[4 * g], hh[4 * g + 1], hh[4 * g + 2], hh[4 * g + 3]);
                        *(uint4*)(H2lo + (size_t)row * 128 + ch * 32 + g * 8) =
                            make_uint4(ll[4 * g], ll[4 * g + 1], ll[4 * g + 2], ll[4 * g + 3]);
                    }
                }
            }
        }
    }
    __syncthreads();

    if (mode == 1) {
        int colc = tid >> 1;
        int r0 = (tid & 1) * 64;
        float s = 0.f, ss = 0.f;
        #pragma unroll 8
        for (int rr = 0; rr < 64; ++rr) {
            float v = vs[(r0 + rr) * 129 + colc];
            s += v; ss += v * v;
        }
        atomicAdd(&g_bnsum[colc], s);
        atomicAdd(&g_bnsq[colc], ss);
        __syncthreads();
    }

    if (tid == 0) MBARRIER_INVAL(smb + SM_MBAR);
    if (wid == 0) TCGEN05_DEALLOC(tmem, 128);
}

// ---------------- final GEMM (lin1 folded BN) + fused lin2 ---------------------
__global__ void __launch_bounds__(256) mma_gemm_final(
    const __nv_bfloat16* __restrict__ Ahi, const __nv_bfloat16* __restrict__ Alo,
    const float* __restrict__ l2W, const float* __restrict__ l2b,
    float* __restrict__ out2)
{
    extern __shared__ char sm[];
    uint32_t smb = smem_to_u32(sm);
    int tid = threadIdx.x;
    int wid = tid >> 5;
    int rowBase = blockIdx.x * 128;

    if (wid == 0) TCGEN05_ALLOC(smb, 128);
    if (tid == 0) MBARRIER_INIT(smb + SM_MBAR, 1);
    if (tid < 128) *(float*)(sm + SM_BIAS + tid * 4) = g_bp[tid];
    __syncthreads();
    uint32_t tmem;
    asm volatile("ld.shared.b32 %0, [%1];" : "=r"(tmem) : "r"(smb));

    for (int c = tid; c < 2048; c += 256) {
        int row = c >> 4;
        int kc  = c & 15;
        uint32_t soff = (uint32_t)(((row >> 3) + ((kc >> 3) << 4)) * 1024 + (row & 7) * 128 + (kc & 7) * 16);
        soff = soff ^ ((soff >> 3) & 0x70);
        size_t gA = ((size_t)rowBase + row) * 128 + kc * 8;
        *(uint4*)(sm + SM_AHI + soff) = *(const uint4*)(Ahi + gA);
        *(uint4*)(sm + SM_ALO + soff) = *(const uint4*)(Alo + gA);
        size_t gB = (size_t)row * 128 + kc * 8;
        *(uint4*)(sm + SM_BHI + soff) = *(const uint4*)(g_Wphi + gB);
        *(uint4*)(sm + SM_BLO + soff) = *(const uint4*)(g_Wplo + gB);
    }
    __syncthreads();
    if (wid == 0) {
        FENCE_PROXY_ASYNC();
        if (elect_one_pred()) {
            uint64_t aH = make_desc(smb + SM_AHI);
            uint64_t aL = make_desc(smb + SM_ALO);
            uint64_t bH = make_desc(smb + SM_BHI);
            uint64_t bL = make_desc(smb + SM_BLO);
            #pragma unroll
            for (int s = 0; s < 8; ++s) {
                uint64_t off = (uint64_t)((s >> 2) * 1024 + (s & 3) * 2);
                mma_f16_ss(tmem, aH + off, bH + off, MMA_IDESC, s != 0);
                mma_f16_ss(tmem, aH + off, bL + off, MMA_IDESC, 1u);
                mma_f16_ss(tmem, aL + off, bH + off, MMA_IDESC, 1u);
            }
            TCGEN05_COMMIT(smb + SM_MBAR);
        }
    }

    MBARRIER_WAIT_PARITY(smb + SM_MBAR, 0);
    TCGEN05_FENCE_AFTER();

    if (tid < 128) {
        int row = rowBase + tid;
        bool active = row < N_NODES;
        float p0 = 0.f, p1 = 0.f;
        for (int ch = 0; ch < 4; ++ch) {
            uint32_t regs[32];
            TCGEN05_LD_X32(regs, tmem + ch * 32);
            TCGEN05_WAIT_LD();
            #pragma unroll
            for (int c = 0; c < 32; ++c) {
                int colc = ch * 32 + c;
                float b = *(const float*)(sm + SM_BIAS + colc * 4);
                float v = fmaxf(__uint_as_float(regs[c]) + b, 0.f);
                p0 += v * l2W[colc * 2 + 0];
                p1 += v * l2W[colc * 2 + 1];
            }
        }
        if (active) {
            out2[(size_t)row * 2 + 0] = p0 + l2b[0];
            out2[(size_t)row * 2 + 1] = p1 + l2b[1];
        }
    }
    __syncthreads();
    if (tid == 0) MBARRIER_INVAL(smb + SM_MBAR);
    if (wid == 0) TCGEN05_DEALLOC(tmem, 128);
}

// ---------------- fold BN into lin1, emit bf16 hi/lo ---------------------------
__global__ void bn_fold_kernel(const float* __restrict__ gamma,
                               const float* __restrict__ beta,
                               const float* __restrict__ lin1W,
                               const float* __restrict__ lin1b)
{
    __shared__ float s_sc[128], s_sh[128];
    int j = threadIdx.x;
    float mean = g_bnsum[j] / (float)N_NODES;
    float var  = g_bnsq[j] / (float)N_NODES - mean * mean;
    float sc = gamma[j] * rsqrtf(var + BN_EPS);
    s_sc[j] = sc;
    s_sh[j] = beta[j] - mean * sc;
    __syncthreads();
    float bp = lin1b[j];
    for (int k = 0; k < 128; k++) {
        float w = lin1W[k * 128 + j];
        float wp = s_sc[k] * w;
        __nv_bfloat16 h = __float2bfloat16_rn(wp);
        g_Wphi[j * 128 + k] = h;
        g_Wplo[j * 128 + k] = __float2bfloat16_rn(wp - __bfloat162float(h));
        bp += s_sh[k] * w;
    }
    g_bp[j] = bp;
}

// ---------------- launch -------------------------------------------------------
extern "C" void kernel_launch(void* const* d_in, const int* in_sizes, int n_in,
                              void* d_out, int out_size)
{
    const float* x      = (const float*)d_in[0];
    const int*   ei     = (const int*)d_in[1];
    const float* W1     = (const float*)d_in[2];
    const float* b1     = (const float*)d_in[3];
    const float* W2     = (const float*)d_in[4];
    const float* b2     = (const float*)d_in[5];
    const float* gamma  = (const float*)d_in[6];
    const float* beta   = (const float*)d_in[7];
    const float* lin1W  = (const float*)d_in[8];
    const float* lin1b  = (const float*)d_in[9];
    const float* lin2W  = (const float*)d_in[10];
    const float* lin2b  = (const float*)d_in[11];
    float* out = (float*)d_out;

    cudaFuncSetAttribute(fused_agg_gemm, cudaFuncAttributeMaxDynamicSharedMemorySize, SM_TOTAL);
    cudaFuncSetAttribute(mma_gemm_final, cudaFuncAttributeMaxDynamicSharedMemorySize, SM_TOTAL);

    float *h1;
    int *cnt, *cursor;
    float *bnsum, *bnsq;
    __nv_bfloat16 *B1hi, *B1lo, *B2hi, *B2lo, *h2hi, *h2lo;
    cudaGetSymbolAddress((void**)&h1,     g_h1);
    cudaGetSymbolAddress((void**)&cnt,    g_cnt);
    cudaGetSymbolAddress((void**)&cursor, g_cursor);
    cudaGetSymbolAddress((void**)&bnsum,  g_bnsum);
    cudaGetSymbolAddress((void**)&bnsq,   g_bnsq);
    cudaGetSymbolAddress((void**)&B1hi,   g_B1hi);
    cudaGetSymbolAddress((void**)&B1lo,   g_B1lo);
    cudaGetSymbolAddress((void**)&B2hi,   g_B2hi);
    cudaGetSymbolAddress((void**)&B2lo,   g_B2lo);
    cudaGetSymbolAddress((void**)&h2hi,   g_h2hi);
    cudaGetSymbolAddress((void**)&h2lo,   g_h2lo);

    const int edgeBlocks = (N_EDGES + 255) / 256;
    const int gemmBlocks = MPAD / 128;   // 391

    cudaMemsetAsync(cnt,    0, sizeof(int) * NREL * N_NODES);
    cudaMemsetAsync(cursor, 0, sizeof(int) * NREL * N_NODES);
    cudaMemsetAsync(bnsum,  0, sizeof(float) * HID);
    cudaMemsetAsync(bnsq,   0, sizeof(float) * HID);

    count_kernel<<<dim3(edgeBlocks, NREL), 256>>>(ei);
    scanA_kernel<<<dim3(NBLK, NREL), 1024>>>();
    scanB_kernel<<<NREL, 64>>>();
    scanC_kernel<<<dim3(NBLK, NREL), 1024>>>();
    fill_kernel<<<dim3(edgeBlocks, NREL), 256>>>(ei);
    bprep_kernel<<<(NREL * HID * HID + 255) / 256, 256>>>(W1, W2);

    // layer 1: gather x -> MMA -> h1 (fp32)
    fused_agg_gemm<<<gemmBlocks, 256, SM_TOTAL>>>(x, B1hi, B1lo, b1,
                                                  h1, nullptr, nullptr, 0);
    // layer 2: gather h1 -> MMA -> h2 hi/lo + BN stats
    fused_agg_gemm<<<gemmBlocks, 256, SM_TOTAL>>>(h1, B2hi, B2lo, b2,
                                                  nullptr, h2hi, h2lo, 1);
    // BN fold -> lin1 weights; lin1 GEMM + fused lin2 epilogue -> out
    bn_fold_kernel<<<1, 128>>>(gamma, beta, lin1W, lin1b);
    mma_gemm_final<<<gemmBlocks, 256, SM_TOTAL>>>(h2hi, h2lo, lin2W, lin2b, out);
}

// round 7
// speedup vs baseline: 1.8744x; 1.8744x over previous
#include <cuda_runtime.h>
#include <cuda_bf16.h>
#include <cstdint>
#include <cstddef>

#define N_NODES 50000
#define N_EDGES 500000
#define HID 128
#define NREL 4
#define BN_EPS 1e-5f
#define NBLK 49            // ceil(50000/1024)
#define MPAD 50048         // 391 * 128

#if defined(__CUDA_ARCH_FEAT_SM103_ALL)
#define HAS_TCGEN05 1
#else
#define HAS_TCGEN05 0
#endif

// ---------------- PTX helpers -------------------------------------------------
__device__ __forceinline__ uint32_t smem_to_u32(const void* p) {
    uint32_t a;
    asm("{ .reg .u64 t; cvta.to.shared.u64 t, %1; cvt.u32.u64 %0, t; }" : "=r"(a) : "l"(p));
    return a;
}
__device__ __forceinline__ uint32_t elect_one_pred() {
    uint32_t pred;
    asm volatile("{\n\t.reg .pred p;\n\telect.sync _|p, 0xFFFFFFFF;\n\tselp.b32 %0, 1, 0, p;\n\t}" : "=r"(pred));
    return pred;
}
#define MBARRIER_INIT(mbar, count) \
    asm volatile("mbarrier.init.shared.b64 [%0], %1;" :: "r"((uint32_t)(mbar)), "r"((uint32_t)(count)) : "memory")
#define MBARRIER_INVAL(mbar) \
    asm volatile("mbarrier.inval.shared.b64 [%0];" :: "r"((uint32_t)(mbar)) : "memory")
#define MBARRIER_WAIT_PARITY(mbar, parity) do { \
    uint32_t _m = (uint32_t)(mbar); uint32_t _p = (uint32_t)(parity); uint32_t _d; \
    asm volatile("{\n\t.reg .pred p;\n\tmbarrier.try_wait.parity.acquire.cta.shared::cta.b64 p, [%1], %2;\n\tselp.b32 %0, 1, 0, p;\n\t}" \
        : "=r"(_d) : "r"(_m), "r"(_p) : "memory"); \
    if (!_d) { \
        asm volatile("{\n\t.reg .pred P1;\n\tWL_%=:\n\tmbarrier.try_wait.parity.acquire.cta.shared::cta.b64 P1, [%0], %1, 0x989680;\n\t@P1 bra.uni WD_%=;\n\tbra.uni WL_%=;\n\tWD_%=:\n\t}" \
            :: "r"(_m), "r"(_p) : "memory"); \
    } \
} while (0)

#if HAS_TCGEN05
#define TCGEN05_ALLOC(smem_addr, nCols) \
    asm volatile("tcgen05.alloc.cta_group::1.sync.aligned.shared::cta.b32 [%0], %1;" \
        :: "r"((uint32_t)(smem_addr)), "r"((uint32_t)(nCols)) : "memory")
#define TCGEN05_DEALLOC(tmem, nCols) \
    asm volatile("tcgen05.dealloc.cta_group::1.sync.aligned.b32 %0, %1;" :: "r"(tmem), "r"((uint32_t)(nCols)))
#define TCGEN05_COMMIT(mbar) \
    asm volatile("tcgen05.commit.cta_group::1.mbarrier::arrive::one.shared::cluster.b64 [%0];" \
        :: "r"((uint32_t)(mbar)) : "memory")
#define TCGEN05_FENCE_AFTER() asm volatile("tcgen05.fence::after_thread_sync;" ::: "memory")
#define TCGEN05_WAIT_LD() asm volatile("tcgen05.wait::ld.sync.aligned;" ::: "memory")
#define TCGEN05_LD_X32(r, addr) \
    asm volatile("tcgen05.ld.sync.aligned.32x32b.x32.b32 " \
        "{%0, %1, %2, %3, %4, %5, %6, %7, %8, %9, %10, %11, %12, %13, %14, %15, " \
        "%16, %17, %18, %19, %20, %21, %22, %23, %24, %25, %26, %27, %28, %29, %30, %31}, [%32];" \
        : "=r"((r)[0]), "=r"((r)[1]), "=r"((r)[2]), "=r"((r)[3]), "=r"((r)[4]), "=r"((r)[5]), "=r"((r)[6]), "=r"((r)[7]), \
          "=r"((r)[8]), "=r"((r)[9]), "=r"((r)[10]), "=r"((r)[11]), "=r"((r)[12]), "=r"((r)[13]), "=r"((r)[14]), "=r"((r)[15]), \
          "=r"((r)[16]), "=r"((r)[17]), "=r"((r)[18]), "=r"((r)[19]), "=r"((r)[20]), "=r"((r)[21]), "=r"((r)[22]), "=r"((r)[23]), \
          "=r"((r)[24]), "=r"((r)[25]), "=r"((r)[26]), "=r"((r)[27]), "=r"((r)[28]), "=r"((r)[29]), "=r"((r)[30]), "=r"((r)[31]) \
        : "r"(addr))
__device__ __forceinline__ void mma_f16_ss(uint32_t d, uint64_t adesc, uint64_t bdesc,
                                           uint32_t idesc, uint32_t en) {
    asm volatile(
        "{\n\t.reg .pred p;\n\tsetp.ne.u32 p, %5, 0;\n\t"
        "tcgen05.mma.cta_group::1.kind::f16 [%0], %1, %2, %3, {%4, %4, %4, %4}, p;\n\t}"
        :: "r"(d), "l"(adesc), "l"(bdesc), "r"(idesc), "r"(0u), "r"(en) : "memory");
}
#else
#define TCGEN05_ALLOC(smem_addr, nCols)  do {} while (0)
#define TCGEN05_DEALLOC(tmem, nCols)     do {} while (0)
#define TCGEN05_COMMIT(mbar)             do {} while (0)
#define TCGEN05_FENCE_AFTER()            do {} while (0)
#define TCGEN05_WAIT_LD()                do {} while (0)
#define TCGEN05_LD_X32(r, addr) \
    do { _Pragma("unroll") for (int _i = 0; _i < 32; ++_i) (r)[_i] = 0u; (void)(addr); } while (0)
__device__ __forceinline__ void mma_f16_ss(uint32_t, uint64_t, uint64_t, uint32_t, uint32_t) {}
#endif

#define FENCE_PROXY_ASYNC() asm volatile("fence.proxy.async.shared::cta;" ::: "memory")

// desc: SW128, version=1, SBO=64, LBO=1 (K-major)
__device__ __forceinline__ uint64_t make_desc(uint32_t addr) {
    uint64_t d = (uint64_t(2) << 61) | (uint64_t(1) << 46) | (uint64_t(64) << 32) | (uint64_t(1) << 16);
    return d | ((uint64_t)(addr >> 4) & 0x3FFF);
}
// idesc: F32 acc, BF16xBF16, M=128, N=128
#define MMA_IDESC 0x8200490u

__device__ __forceinline__ unsigned bf16_us(__nv_bfloat16 h) { return (unsigned)__bfloat16_as_ushort(h); }

// ---------------- scratch -----------------------------------------------------
__device__ int   g_cnt[NREL * N_NODES];
__device__ int   g_cursor[NREL * N_NODES];
__device__ float g_dinv[NREL * N_NODES];
__device__ int   g_rowptr[NREL * (N_NODES + 1)];
__device__ int   g_col[NREL * N_EDGES];
__device__ int   g_bsum[NREL * 64];
__device__ __nv_bfloat16 g_agghi[(size_t)NREL * MPAD * HID];
__device__ __nv_bfloat16 g_agglo[(size_t)NREL * MPAD * HID];
__device__ __nv_bfloat16 g_B1hi[NREL * HID * HID];
__device__ __nv_bfloat16 g_B1lo[NREL * HID * HID];
__device__ __nv_bfloat16 g_B2hi[NREL * HID * HID];
__device__ __nv_bfloat16 g_B2lo[NREL * HID * HID];
__device__ __nv_bfloat16 g_Wphi[HID * HID];
__device__ __nv_bfloat16 g_Wplo[HID * HID];
__device__ __nv_bfloat16 g_h2hi[(size_t)MPAD * HID];
__device__ __nv_bfloat16 g_h2lo[(size_t)MPAD * HID];
__device__ float g_h1[(size_t)N_NODES * HID];
__device__ float g_bnsum[HID];
__device__ float g_bnsq[HID];
__device__ float g_bp[HID];

// ---------------- CSR build ---------------------------------------------------
// int4-vectorized degree count: thread handles 4 edges
__global__ void count_kernel(const int* __restrict__ ei) {
    int r = blockIdx.y;
    int e4 = blockIdx.x * blockDim.x + threadIdx.x;
    if (e4 >= N_EDGES / 4) return;
    int4 d = ((const int4*)(ei + ((size_t)r * 2 + 1) * N_EDGES))[e4];
    int* cnt = g_cnt + r * N_NODES;
    atomicAdd(&cnt[d.x], 1);
    atomicAdd(&cnt[d.y], 1);
    atomicAdd(&cnt[d.z], 1);
    atomicAdd(&cnt[d.w], 1);
}

// block-local inclusive scan; also writes dinv and zeroes cursor
__global__ void scanA_kernel() {
    int r = blockIdx.y, blk = blockIdx.x, tid = threadIdx.x;
    __shared__ int s[1024];
    int i = blk * 1024 + tid;
    int v0 = (i < N_NODES) ? g_cnt[r * N_NODES + i] : 0;
    s[tid] = v0;
    #pragma unroll
    for (int d = 1; d < 1024; d <<= 1) {
        __syncthreads();
        int t = (tid >= d) ? s[tid - d] : 0;
        __syncthreads();
        s[tid] += t;
    }
    __syncthreads();
    if (i < N_NODES) {
        g_rowptr[r * (N_NODES + 1) + i + 1] = s[tid];
        g_dinv[r * N_NODES + i] = rsqrtf((float)v0 + 1.0f);
        g_cursor[r * N_NODES + i] = 0;
    }
    if (tid == 1023) g_bsum[r * 64 + blk] = s[tid];
}

// finalize: each block adds the prefix of earlier block sums (49 partials)
__global__ void scan_fin_kernel() {
    int r = blockIdx.y, blk = blockIdx.x, tid = threadIdx.x;
    __shared__ int s[64];
    __shared__ int off;
    if (tid < 64) s[tid] = (tid < NBLK) ? g_bsum[r * 64 + tid] : 0;
    __syncthreads();
    if (tid == 0) {
        int acc = 0;
        for (int t = 0; t < blk; ++t) acc += s[t];
        off = acc;
        if (blk == 0) g_rowptr[r * (N_NODES + 1)] = 0;
    }
    __syncthreads();
    int i = blk * 1024 + tid;
    if (i < N_NODES)
        g_rowptr[r * (N_NODES + 1) + i + 1] += off;
}

// int4-vectorized CSR fill
__global__ void fill_kernel(const int* __restrict__ ei) {
    int r = blockIdx.y;
    int e4 = blockIdx.x * blockDim.x + threadIdx.x;
    if (e4 >= N_EDGES / 4) return;
    int4 sv = ((const int4*)(ei + (size_t)r * 2 * N_EDGES))[e4];
    int4 dv = ((const int4*)(ei + ((size_t)r * 2 + 1) * N_EDGES))[e4];
    const int* rp = g_rowptr + r * (N_NODES + 1);
    int* cur = g_cursor + r * N_NODES;
    int* col = g_col + (size_t)r * N_EDGES;
    int p;
    p = rp[dv.x] + atomicAdd(&cur[dv.x], 1); col[p] = sv.x;
    p = rp[dv.y] + atomicAdd(&cur[dv.y], 1); col[p] = sv.y;
    p = rp[dv.z] + atomicAdd(&cur[dv.z], 1); col[p] = sv.z;
    p = rp[dv.w] + atomicAdd(&cur[dv.w], 1); col[p] = sv.w;
}

// ---------------- weight prep (also zeroes BN accumulators) --------------------
__global__ void bprep_kernel(const float* __restrict__ W1, const float* __restrict__ W2) {
    int i = blockIdx.x * blockDim.x + threadIdx.x;
    if (blockIdx.x == 0 && threadIdx.x < HID) {
        g_bnsum[threadIdx.x] = 0.f;
        g_bnsq[threadIdx.x]  = 0.f;
    }
    if (i >= NREL * HID * HID) return;
    int r = i >> 14, rem = i & 16383;
    int n = rem >> 7, k = rem & 127;
    size_t src = (size_t)r * 16384 + k * 128 + n;
    size_t dst = (size_t)r * 16384 + n * 128 + k;
    float v1 = W1[src];
    __nv_bfloat16 h1 = __float2bfloat16_rn(v1);
    g_B1hi[dst] = h1;
    g_B1lo[dst] = __float2bfloat16_rn(v1 - __bfloat162float(h1));
    float v2 = W2[src];
    __nv_bfloat16 h2 = __float2bfloat16_rn(v2);
    g_B2hi[dst] = h2;
    g_B2lo[dst] = __float2bfloat16_rn(v2 - __bfloat162float(h2));
}

// ---------------- CSR aggregate (all relations per warp) -> bf16 hi/lo ---------
__global__ void aggregate_kernel(const float* __restrict__ X) {
    int node = blockIdx.x * 8 + (threadIdx.x >> 5);
    if (node >= N_NODES) return;
    int lane = threadIdx.x & 31;
    const float4* x4 = (const float4*)X;
    float4 xv = x4[(size_t)node * 32 + lane];

    #pragma unroll
    for (int r = 0; r < NREL; ++r) {
        const float* dinv = g_dinv + r * N_NODES;
        float dd = dinv[node];
        float4 acc;
        acc.x = dd * xv.x; acc.y = dd * xv.y; acc.z = dd * xv.z; acc.w = dd * xv.w;
        int beg = g_rowptr[r * (N_NODES + 1) + node];
        int end = g_rowptr[r * (N_NODES + 1) + node + 1];
        const int* col = g_col + (size_t)r * N_EDGES;
        int j = beg;
        for (; j + 4 <= end; j += 4) {
            int s0 = col[j], s1 = col[j + 1], s2 = col[j + 2], s3 = col[j + 3];
            float w0 = dinv[s0], w1 = dinv[s1], w2 = dinv[s2], w3 = dinv[s3];
            float4 v0 = x4[(size_t)s0 * 32 + lane];
            float4 v1 = x4[(size_t)s1 * 32 + lane];
            float4 v2 = x4[(size_t)s2 * 32 + lane];
            float4 v3 = x4[(size_t)s3 * 32 + lane];
            acc.x += w0 * v0.x + w1 * v1.x + w2 * v2.x + w3 * v3.x;
            acc.y += w0 * v0.y + w1 * v1.y + w2 * v2.y + w3 * v3.y;
            acc.z += w0 * v0.z + w1 * v1.z + w2 * v2.z + w3 * v3.z;
            acc.w += w0 * v0.w + w1 * v1.w + w2 * v2.w + w3 * v3.w;
        }
        for (; j < end; ++j) {
            int s0 = col[j];
            float w0 = dinv[s0];
            float4 v0 = x4[(size_t)s0 * 32 + lane];
            acc.x += w0 * v0.x; acc.y += w0 * v0.y;
            acc.z += w0 * v0.z; acc.w += w0 * v0.w;
        }
        acc.x *= dd; acc.y *= dd; acc.z *= dd; acc.w *= dd;
        float v[4] = { acc.x, acc.y, acc.z, acc.w };
        unsigned hh[2], ll[2];
        #pragma unroll
        for (int p = 0; p < 2; p++) {
            __nv_bfloat16 h0 = __float2bfloat16_rn(v[2 * p]);
            __nv_bfloat16 h1 = __float2bfloat16_rn(v[2 * p + 1]);
            __nv_bfloat16 l0 = __float2bfloat16_rn(v[2 * p] - __bfloat162float(h0));
            __nv_bfloat16 l1 = __float2bfloat16_rn(v[2 * p + 1] - __bfloat162float(h1));
            hh[p] = bf16_us(h0) | (bf16_us(h1) << 16);
            ll[p] = bf16_us(l0) | (bf16_us(l1) << 16);
        }
        size_t base = ((size_t)r * MPAD + node) * 128 + 4 * lane;
        *(uint2*)(g_agghi + base) = make_uint2(hh[0], hh[1]);
        *(uint2*)(g_agglo + base) = make_uint2(ll[0], ll[1]);
    }
}

// ---------------- tcgen05 split-bf16 GEMM -------------------------------------
// modes: 0: Hout = relu(D)   1: H2 split + BN stats   2: fused lin2 -> out2
#define SM_AHI 1024
#define SM_ALO (1024 + 32768)
#define SM_BHI (1024 + 65536)
#define SM_BLO (1024 + 98304)
#define SM_TOTAL (1024 + 131072)
#define SM_MBAR 8
#define SM_BIAS 16

__global__ void __launch_bounds__(256) mma_gemm(
    const __nv_bfloat16* __restrict__ Ahi, const __nv_bfloat16* __restrict__ Alo,
    const __nv_bfloat16* __restrict__ Bhi, const __nv_bfloat16* __restrict__ Blo,
    const float* __restrict__ bias, int nrel,
    float* __restrict__ Hout,
    __nv_bfloat16* __restrict__ H2hi, __nv_bfloat16* __restrict__ H2lo,
    const float* __restrict__ l2W, const float* __restrict__ l2b,
    float* __restrict__ out2, int mode)
{
    extern __shared__ char sm[];
    uint32_t smb = smem_to_u32(sm);
    int tid = threadIdx.x;
    int wid = tid >> 5;
    int rowBase = blockIdx.x * 128;

    if (wid == 0) TCGEN05_ALLOC(smb, 128);
    if (tid == 0) MBARRIER_INIT(smb + SM_MBAR, 1);
    if (tid < 128) {
        float s = 0.f;
        for (int r = 0; r < nrel; r++) s += bias[r * 128 + tid];
        *(float*)(sm + SM_BIAS + tid * 4) = s;
    }
    __syncthreads();
    uint32_t tmem;
    asm volatile("ld.shared.b32 %0, [%1];" : "=r"(tmem) : "r"(smb));

    for (int r = 0; r < nrel; ++r) {
        if (r) {
            MBARRIER_WAIT_PARITY(smb + SM_MBAR, (r - 1) & 1);
            __syncthreads();
        }
        for (int c = tid; c < 2048; c += 256) {
            int row = c >> 4;
            int kc  = c & 15;
            uint32_t soff = (uint32_t)(((row >> 3) + ((kc >> 3) << 4)) * 1024 + (row & 7) * 128 + (kc & 7) * 16);
            soff = soff ^ ((soff >> 3) & 0x70);
            size_t gA = ((size_t)r * MPAD + rowBase + row) * 128 + kc * 8;
            *(uint4*)(sm + SM_AHI + soff) = *(const uint4*)(Ahi + gA);
            *(uint4*)(sm + SM_ALO + soff) = *(const uint4*)(Alo + gA);
            size_t gB = ((size_t)r * 128 + row) * 128 + kc * 8;
            *(uint4*)(sm + SM_BHI + soff) = *(const uint4*)(Bhi + gB);
            *(uint4*)(sm + SM_BLO + soff) = *(const uint4*)(Blo + gB);
        }
        __syncthreads();
        if (wid == 0) {
            FENCE_PROXY_ASYNC();
            if (elect_one_pred()) {
                uint64_t aH = make_desc(smb + SM_AHI);
                uint64_t aL = make_desc(smb + SM_ALO);
                uint64_t bH = make_desc(smb + SM_BHI);
                uint64_t bL = make_desc(smb + SM_BLO);
                #pragma unroll
                for (int s = 0; s < 8; ++s) {
                    uint64_t off = (uint64_t)((s >> 2) * 1024 + (s & 3) * 2);
                    mma_f16_ss(tmem, aH + off, bH + off, MMA_IDESC, !(r == 0 && s == 0));
                    mma_f16_ss(tmem, aH + off, bL + off, MMA_IDESC, 1u);
                    mma_f16_ss(tmem, aL + off, bH + off, MMA_IDESC, 1u);
                }
                TCGEN05_COMMIT(smb + SM_MBAR);
            }
        }
    }

    MBARRIER_WAIT_PARITY(smb + SM_MBAR, (nrel - 1) & 1);
    TCGEN05_FENCE_AFTER();

    float* vs = (float*)(sm + SM_AHI);   // [128][129] BN scratch (mode 1)

    if (tid < 128) {
        int row = rowBase + tid;
        bool active = row < N_NODES;
        float p0 = 0.f, p1 = 0.f;
        for (int ch = 0; ch < 4; ++ch) {
            uint32_t regs[32];
            TCGEN05_LD_X32(regs, tmem + ch * 32);
            TCGEN05_WAIT_LD();
            float v[32];
            #pragma unroll
            for (int c = 0; c < 32; ++c) {
                float b = *(const float*)(sm + SM_BIAS + (ch * 32 + c) * 4);
                v[c] = active ? fmaxf(__uint_as_float(regs[c]) + b, 0.f) : 0.f;
            }
            if (mode == 0) {
                if (active) {
                    #pragma unroll
                    for (int g = 0; g < 8; ++g)
                        *(float4*)(Hout + (size_t)row * 128 + ch * 32 + g * 4) =
                            make_float4(v[g * 4], v[g * 4 + 1], v[g * 4 + 2], v[g * 4 + 3]);
                }
            } else if (mode == 1) {
                #pragma unroll
                for (int c = 0; c < 32; ++c) vs[tid * 129 + ch * 32 + c] = v[c];
                if (active) {
                    unsigned hh[16], ll[16];
                    #pragma unroll
                    for (int p = 0; p < 16; ++p) {
                        __nv_bfloat16 h0 = __float2bfloat16_rn(v[2 * p]);
                        __nv_bfloat16 h1 = __float2bfloat16_rn(v[2 * p + 1]);
                        __nv_bfloat16 l0 = __float2bfloat16_rn(v[2 * p] - __bfloat162float(h0));
                        __nv_bfloat16 l1 = __float2bfloat16_rn(v[2 * p + 1] - __bfloat162float(h1));
                        hh[p] = bf16_us(h0) | (bf16_us(h1) << 16);
                        ll[p] = bf16_us(l0) | (bf16_us(l1) << 16);
                    }
                    #pragma unroll
                    for (int g = 0; g < 4; ++g) {
                        *(uint4*)(H2hi + (size_t)row * 128 + ch * 32 + g * 8) =
                            make_uint4(hh[4 * g], hh[4 * g + 1], hh[4 * g + 2], hh[4 * g + 3]);
                        *(uint4*)(H2lo + (size_t)row * 128 + ch * 32 + g * 8) =
                            make_uint4(ll[4 * g], ll[4 * g + 1], ll[4 * g + 2], ll[4 * g + 3]);
                    }
                }
            } else {
                #pragma unroll
                for (int c = 0; c < 32; ++c) {
                    int col = ch * 32 + c;
                    p0 += v[c] * l2W[col * 2 + 0];
                    p1 += v[c] * l2W[col * 2 + 1];
                }
            }
        }
        if (mode == 2 && active) {
            out2[(size_t)row * 2 + 0] = p0 + l2b[0];
            out2[(size_t)row * 2 + 1] = p1 + l2b[1];
        }
    }
    __syncthreads();

    if (mode == 1) {
        int col = tid >> 1;
        int r0 = (tid & 1) * 64;
        float s = 0.f, ss = 0.f;
        #pragma unroll 8
        for (int rr = 0; rr < 64; ++rr) {
            float v = vs[(r0 + rr) * 129 + col];
            s += v; ss += v * v;
        }
        atomicAdd(&g_bnsum[col], s);
        atomicAdd(&g_bnsq[col], ss);
        __syncthreads();
    }

    if (tid == 0) MBARRIER_INVAL(smb + SM_MBAR);
    if (wid == 0) TCGEN05_DEALLOC(tmem, 128);
}

// ---------------- fold BN into lin1, emit bf16 hi/lo ---------------------------
__global__ void bn_fold_kernel(const float* __restrict__ gamma,
                               const float* __restrict__ beta,
                               const float* __restrict__ lin1W,
                               const float* __restrict__ lin1b)
{
    __shared__ float s_sc[128], s_sh[128];
    int j = threadIdx.x;
    float mean = g_bnsum[j] / (float)N_NODES;
    float var  = g_bnsq[j] / (float)N_NODES - mean * mean;
    float sc = gamma[j] * rsqrtf(var + BN_EPS);
    s_sc[j] = sc;
    s_sh[j] = beta[j] - mean * sc;
    __syncthreads();
    float bp = lin1b[j];
    for (int k = 0; k < 128; k++) {
        float w = lin1W[k * 128 + j];
        float wp = s_sc[k] * w;
        __nv_bfloat16 h = __float2bfloat16_rn(wp);
        g_Wphi[j * 128 + k] = h;
        g_Wplo[j * 128 + k] = __float2bfloat16_rn(wp - __bfloat162float(h));
        bp += s_sh[k] * w;
    }
    g_bp[j] = bp;
}

// ---------------- launch -------------------------------------------------------
extern "C" void kernel_launch(void* const* d_in, const int* in_sizes, int n_in,
                              void* d_out, int out_size)
{
    const float* x      = (const float*)d_in[0];
    const int*   ei     = (const int*)d_in[1];
    const float* W1     = (const float*)d_in[2];
    const float* b1     = (const float*)d_in[3];
    const float* W2     = (const float*)d_in[4];
    const float* b2     = (const float*)d_in[5];
    const float* gamma  = (const float*)d_in[6];
    const float* beta   = (const float*)d_in[7];
    const float* lin1W  = (const float*)d_in[8];
    const float* lin1b  = (const float*)d_in[9];
    const float* lin2W  = (const float*)d_in[10];
    const float* lin2b  = (const float*)d_in[11];
    float* out = (float*)d_out;

    cudaFuncSetAttribute(mma_gemm, cudaFuncAttributeMaxDynamicSharedMemorySize, SM_TOTAL);

    float *h1, *bp;
    int *cnt;
    __nv_bfloat16 *agghi, *agglo, *B1hi, *B1lo, *B2hi, *B2lo, *Wphi, *Wplo, *h2hi, *h2lo;
    cudaGetSymbolAddress((void**)&h1,     g_h1);
    cudaGetSymbolAddress((void**)&bp,     g_bp);
    cudaGetSymbolAddress((void**)&cnt,    g_cnt);
    cudaGetSymbolAddress((void**)&agghi,  g_agghi);
    cudaGetSymbolAddress((void**)&agglo,  g_agglo);
    cudaGetSymbolAddress((void**)&B1hi,   g_B1hi);
    cudaGetSymbolAddress((void**)&B1lo,   g_B1lo);
    cudaGetSymbolAddress((void**)&B2hi,   g_B2hi);
    cudaGetSymbolAddress((void**)&B2lo,   g_B2lo);
    cudaGetSymbolAddress((void**)&Wphi,   g_Wphi);
    cudaGetSymbolAddress((void**)&Wplo,   g_Wplo);
    cudaGetSymbolAddress((void**)&h2hi,   g_h2hi);
    cudaGetSymbolAddress((void**)&h2lo,   g_h2lo);

    const int edge4Blocks = (N_EDGES / 4 + 255) / 256;   // 489
    const int aggBlocks   = (N_NODES + 7) / 8;           // 6250
    const int gemmBlocks  = MPAD / 128;                  // 391

    cudaMemsetAsync(cnt, 0, sizeof(int) * NREL * N_NODES);

    count_kernel<<<dim3(edge4Blocks, NREL), 256>>>(ei);
    scanA_kernel<<<dim3(NBLK, NREL), 1024>>>();
    scan_fin_kernel<<<dim3(NBLK, NREL), 1024>>>();
    fill_kernel<<<dim3(edge4Blocks, NREL), 256>>>(ei);
    bprep_kernel<<<(NREL * HID * HID + 255) / 256, 256>>>(W1, W2);

    // layer 1
    aggregate_kernel<<<aggBlocks, 256>>>(x);
    mma_gemm<<<gemmBlocks, 256, SM_TOTAL>>>(agghi, agglo, B1hi, B1lo, b1, NREL,
                                            h1, nullptr, nullptr,
                                            nullptr, nullptr, nullptr, 0);
    // layer 2 (BN stats fused)
    aggregate_kernel<<<aggBlocks, 256>>>(h1);
    mma_gemm<<<gemmBlocks, 256, SM_TOTAL>>>(agghi, agglo, B2hi, B2lo, b2, NREL,
                                            nullptr, h2hi, h2lo,
                                            nullptr, nullptr, nullptr, 1);
    // BN fold -> lin1 bf16 weights; lin1 GEMM + fused lin2 epilogue
    bn_fold_kernel<<<1, 128>>>(gamma, beta, lin1W, lin1b);
    mma_gemm<<<gemmBlocks, 256, SM_TOTAL>>>(h2hi, h2lo, Wphi, Wplo, bp, 1,
                                            nullptr, nullptr, nullptr,
                                            lin2W, lin2b, out, 2);
}

// round 9
// speedup vs baseline: 1.8787x; 1.0023x over previous
#include <cuda_runtime.h>
#include <cuda_bf16.h>
#include <cuda_fp16.h>
#include <cstdint>
#include <cstddef>

#define N_NODES 50000
#define N_EDGES 500000
#define HID 128
#define NREL 4
#define BN_EPS 1e-5f
#define NBLK 49            // ceil(50000/1024)
#define MPAD 50048         // 391 * 128

#if defined(__CUDA_ARCH_FEAT_SM103_ALL)
#define HAS_TCGEN05 1
#else
#define HAS_TCGEN05 0
#endif

// ---------------- PTX helpers -------------------------------------------------
__device__ __forceinline__ uint32_t smem_to_u32(const void* p) {
    uint32_t a;
    asm("{ .reg .u64 t; cvta.to.shared.u64 t, %1; cvt.u32.u64 %0, t; }" : "=r"(a) : "l"(p));
    return a;
}
__device__ __forceinline__ uint32_t elect_one_pred() {
    uint32_t pred;
    asm volatile("{\n\t.reg .pred p;\n\telect.sync _|p, 0xFFFFFFFF;\n\tselp.b32 %0, 1, 0, p;\n\t}" : "=r"(pred));
    return pred;
}
#define MBARRIER_INIT(mbar, count) \
    asm volatile("mbarrier.init.shared.b64 [%0], %1;" :: "r"((uint32_t)(mbar)), "r"((uint32_t)(count)) : "memory")
#define MBARRIER_INVAL(mbar) \
    asm volatile("mbarrier.inval.shared.b64 [%0];" :: "r"((uint32_t)(mbar)) : "memory")
#define MBARRIER_WAIT_PARITY(mbar, parity) do { \
    uint32_t _m = (uint32_t)(mbar); uint32_t _p = (uint32_t)(parity); uint32_t _d; \
    asm volatile("{\n\t.reg .pred p;\n\tmbarrier.try_wait.parity.acquire.cta.shared::cta.b64 p, [%1], %2;\n\tselp.b32 %0, 1, 0, p;\n\t}" \
        : "=r"(_d) : "r"(_m), "r"(_p) : "memory"); \
    if (!_d) { \
        asm volatile("{\n\t.reg .pred P1;\n\tWL_%=:\n\tmbarrier.try_wait.parity.acquire.cta.shared::cta.b64 P1, [%0], %1, 0x989680;\n\t@P1 bra.uni WD_%=;\n\tbra.uni WL_%=;\n\tWD_%=:\n\t}" \
            :: "r"(_m), "r"(_p) : "memory"); \
    } \
} while (0)

#if HAS_TCGEN05
#define TCGEN05_ALLOC(smem_addr, nCols) \
    asm volatile("tcgen05.alloc.cta_group::1.sync.aligned.shared::cta.b32 [%0], %1;" \
        :: "r"((uint32_t)(smem_addr)), "r"((uint32_t)(nCols)) : "memory")
#define TCGEN05_DEALLOC(tmem, nCols) \
    asm volatile("tcgen05.dealloc.cta_group::1.sync.aligned.b32 %0, %1;" :: "r"(tmem), "r"((uint32_t)(nCols)))
#define TCGEN05_COMMIT(mbar) \
    asm volatile("tcgen05.commit.cta_group::1.mbarrier::arrive::one.shared::cluster.b64 [%0];" \
        :: "r"((uint32_t)(mbar)) : "memory")
#define TCGEN05_FENCE_AFTER() asm volatile("tcgen05.fence::after_thread_sync;" ::: "memory")
#define TCGEN05_WAIT_LD() asm volatile("tcgen05.wait::ld.sync.aligned;" ::: "memory")
#define TCGEN05_LD_X32(r, addr) \
    asm volatile("tcgen05.ld.sync.aligned.32x32b.x32.b32 " \
        "{%0, %1, %2, %3, %4, %5, %6, %7, %8, %9, %10, %11, %12, %13, %14, %15, " \
        "%16, %17, %18, %19, %20, %21, %22, %23, %24, %25, %26, %27, %28, %29, %30, %31}, [%32];" \
        : "=r"((r)[0]), "=r"((r)[1]), "=r"((r)[2]), "=r"((r)[3]), "=r"((r)[4]), "=r"((r)[5]), "=r"((r)[6]), "=r"((r)[7]), \
          "=r"((r)[8]), "=r"((r)[9]), "=r"((r)[10]), "=r"((r)[11]), "=r"((r)[12]), "=r"((r)[13]), "=r"((r)[14]), "=r"((r)[15]), \
          "=r"((r)[16]), "=r"((r)[17]), "=r"((r)[18]), "=r"((r)[19]), "=r"((r)[20]), "=r"((r)[21]), "=r"((r)[22]), "=r"((r)[23]), \
          "=r"((r)[24]), "=r"((r)[25]), "=r"((r)[26]), "=r"((r)[27]), "=r"((r)[28]), "=r"((r)[29]), "=r"((r)[30]), "=r"((r)[31]) \
        : "r"(addr))
__device__ __forceinline__ void mma_f16_ss(uint32_t d, uint64_t adesc, uint64_t bdesc,
                                           uint32_t idesc, uint32_t en) {
    asm volatile(
        "{\n\t.reg .pred p;\n\tsetp.ne.u32 p, %5, 0;\n\t"
        "tcgen05.mma.cta_group::1.kind::f16 [%0], %1, %2, %3, {%4, %4, %4, %4}, p;\n\t}"
        :: "r"(d), "l"(adesc), "l"(bdesc), "r"(idesc), "r"(0u), "r"(en) : "memory");
}
#else
#define TCGEN05_ALLOC(smem_addr, nCols)  do {} while (0)
#define TCGEN05_DEALLOC(tmem, nCols)     do {} while (0)
#define TCGEN05_COMMIT(mbar)             do {} while (0)
#define TCGEN05_FENCE_AFTER()            do {} while (0)
#define TCGEN05_WAIT_LD()                do {} while (0)
#define TCGEN05_LD_X32(r, addr) \
    do { _Pragma("unroll") for (int _i = 0; _i < 32; ++_i) (r)[_i] = 0u; (void)(addr); } while (0)
__device__ __forceinline__ void mma_f16_ss(uint32_t, uint64_t, uint64_t, uint32_t, uint32_t) {}
#endif

#define FENCE_PROXY_ASYNC() asm volatile("fence.proxy.async.shared::cta;" ::: "memory")

// desc: SW128, version=1, SBO=64, LBO=1 (K-major)
__device__ __forceinline__ uint64_t make_desc(uint32_t addr) {
    uint64_t d = (uint64_t(2) << 61) | (uint64_t(1) << 46) | (uint64_t(64) << 32) | (uint64_t(1) << 16);
    return d | ((uint64_t)(addr >> 4) & 0x3FFF);
}
// idesc: F32 acc, BF16xBF16, M=128, N=128
#define MMA_IDESC 0x8200490u

__device__ __forceinline__ unsigned bf16_us(__nv_bfloat16 h) { return (unsigned)__bfloat16_as_ushort(h); }

// ---------------- scratch -----------------------------------------------------
__device__ int    g_cnt[NREL * N_NODES];
__device__ float  g_dinv[NREL * N_NODES];
__device__ int    g_rowptr[NREL * (N_NODES + 1)];
__device__ int    g_col[NREL * N_EDGES];
__device__ int    g_epos[NREL * N_EDGES];
__device__ int    g_bsum[NREL * 64];
__device__ __half g_xh[(size_t)N_NODES * HID];
__device__ __half g_h1h[(size_t)N_NODES * HID];
__device__ __nv_bfloat16 g_agghi[(size_t)NREL * MPAD * HID];
__device__ __nv_bfloat16 g_agglo[(size_t)NREL * MPAD * HID];
__device__ __nv_bfloat16 g_B1hi[NREL * HID * HID];
__device__ __nv_bfloat16 g_B1lo[NREL * HID * HID];
__device__ __nv_bfloat16 g_B2hi[NREL * HID * HID];
__device__ __nv_bfloat16 g_B2lo[NREL * HID * HID];
__device__ __nv_bfloat16 g_Wphi[HID * HID];
__device__ __nv_bfloat16 g_Wplo[HID * HID];
__device__ __nv_bfloat16 g_h2hi[(size_t)MPAD * HID];
__device__ __nv_bfloat16 g_h2lo[(size_t)MPAD * HID];
__device__ float  g_bnsum[HID];
__device__ float  g_bnsq[HID];
__device__ float  g_bp[HID];

// ---------------- x -> fp16 ----------------------------------------------------
__global__ void xconv_kernel(const float* __restrict__ X) {
    int i = blockIdx.x * blockDim.x + threadIdx.x;   // over 1.6M float4
    if (i >= N_NODES * HID / 4) return;
    float4 v = ((const float4*)X)[i];
    __half2 a = __floats2half2_rn(v.x, v.y);
    __half2 b = __floats2half2_rn(v.z, v.w);
    ((uint2*)g_xh)[i] = make_uint2(*(uint32_t*)&a, *(uint32_t*)&b);
}

// ---------------- CSR build ---------------------------------------------------
// count + record each edge's position in its dst bucket (atomic-free fill later)
__global__ void count_kernel(const int* __restrict__ ei) {
    int r = blockIdx.y;
    int e4 = blockIdx.x * blockDim.x + threadIdx.x;
    if (e4 >= N_EDGES / 4) return;
    int4 d = ((const int4*)(ei + ((size_t)r * 2 + 1) * N_EDGES))[e4];
    int* cnt = g_cnt + r * N_NODES;
    int4 p;
    p.x = atomicAdd(&cnt[d.x], 1);
    p.y = atomicAdd(&cnt[d.y], 1);
    p.z = atomicAdd(&cnt[d.z], 1);
    p.w = atomicAdd(&cnt[d.w], 1);
    ((int4*)(g_epos + (size_t)r * N_EDGES))[e4] = p;
}

__global__ void scanA_kernel() {
    int r = blockIdx.y, blk = blockIdx.x, tid = threadIdx.x;
    __shared__ int s[1024];
    int i = blk * 1024 + tid;
    int v0 = (i < N_NODES) ? g_cnt[r * N_NODES + i] : 0;
    s[tid] = v0;
    #pragma unroll
    for (int d = 1; d < 1024; d <<= 1) {
        __syncthreads();
        int t = (tid >= d) ? s[tid - d] : 0;
        __syncthreads();
        s[tid] += t;
    }
    __syncthreads();
    if (i < N_NODES) {
        g_rowptr[r * (N_NODES + 1) + i + 1] = s[tid];
        g_dinv[r * N_NODES + i] = rsqrtf((float)v0 + 1.0f);
    }
    if (tid == 1023) g_bsum[r * 64 + blk] = s[tid];
}

__global__ void scan_fin_kernel() {
    int r = blockIdx.y, blk = blockIdx.x, tid = threadIdx.x;
    __shared__ int s[64];
    __shared__ int off;
    if (tid < 64) s[tid] = (tid < NBLK) ? g_bsum[r * 64 + tid] : 0;
    __syncthreads();
    if (tid == 0) {
        int acc = 0;
        for (int t = 0; t < blk; ++t) acc += s[t];
        off = acc;
        if (blk == 0) g_rowptr[r * (N_NODES + 1)] = 0;
    }
    __syncthreads();
    int i = blk * 1024 + tid;
    if (i < N_NODES)
        g_rowptr[r * (N_NODES + 1) + i + 1] += off;
}

__global__ void fill_kernel(const int* __restrict__ ei) {
    int r = blockIdx.y;
    int e4 = blockIdx.x * blockDim.x + threadIdx.x;
    if (e4 >= N_EDGES / 4) return;
    int4 sv = ((const int4*)(ei + (size_t)r * 2 * N_EDGES))[e4];
    int4 dv = ((const int4*)(ei + ((size_t)r * 2 + 1) * N_EDGES))[e4];
    int4 pv = ((const int4*)(g_epos + (size_t)r * N_EDGES))[e4];
    const int* rp = g_rowptr + r * (N_NODES + 1);
    int* col = g_col + (size_t)r * N_EDGES;
    col[rp[dv.x] + pv.x] = sv.x;
    col[rp[dv.y] + pv.y] = sv.y;
    col[rp[dv.z] + pv.z] = sv.z;
    col[rp[dv.w] + pv.w] = sv.w;
}

// ---------------- weight prep: W[r][k][n] fp32 -> B[r][n][k] bf16 hi/lo --------
__global__ void bprep_kernel(const float* __restrict__ W1, const float* __restrict__ W2) {
    int i = blockIdx.x * blockDim.x + threadIdx.x;
    if (blockIdx.x == 0 && threadIdx.x < HID) {
        g_bnsum[threadIdx.x] = 0.f;
        g_bnsq[threadIdx.x]  = 0.f;
    }
    if (i >= NREL * HID * HID) return;
    int r = i >> 14, rem = i & 16383;
    int n = rem >> 7, k = rem & 127;
    size_t src = (size_t)r * 16384 + k * 128 + n;
    size_t dst = (size_t)r * 16384 + n * 128 + k;
    float v1 = W1[src];
    __nv_bfloat16 h1 = __float2bfloat16_rn(v1);
    g_B1hi[dst] = h1;
    g_B1lo[dst] = __float2bfloat16_rn(v1 - __bfloat162float(h1));
    float v2 = W2[src];
    __nv_bfloat16 h2 = __float2bfloat16_rn(v2);
    g_B2hi[dst] = h2;
    g_B2lo[dst] = __float2bfloat16_rn(v2 - __bfloat162float(h2));
}

// ---------------- CSR aggregate: fp16 gather, fp32 accum, bf16 hi/lo out -------
__global__ void aggregate_kernel(const __half* __restrict__ Xh) {
    int node = blockIdx.x * 8 + (threadIdx.x >> 5);
    if (node >= N_NODES) return;
    int lane = threadIdx.x & 31;
    const uint2* x2 = (const uint2*)Xh;   // 32 uint2 per row (4 feats each)
    uint2 xv = x2[(size_t)node * 32 + lane];
    float2 xa = __half22float2(*(__half2*)&xv.x);
    float2 xb = __half22float2(*(__half2*)&xv.y);

    for (int r = 0; r < NREL; ++r) {
        const float* dinv = g_dinv + r * N_NODES;
        float dd = dinv[node];
        float4 acc = make_float4(dd * xa.x, dd * xa.y, dd * xb.x, dd * xb.y);
        int beg = g_rowptr[r * (N_NODES + 1) + node];
        int end = g_rowptr[r * (N_NODES + 1) + node + 1];
        const int* col = g_col + (size_t)r * N_EDGES;
        int j = beg;
        for (; j + 4 <= end; j += 4) {
            int s0 = col[j], s1 = col[j + 1], s2 = col[j + 2], s3 = col[j + 3];
            float w0 = dinv[s0], w1 = dinv[s1], w2 = dinv[s2], w3 = dinv[s3];
            uint2 u0 = x2[(size_t)s0 * 32 + lane];
            uint2 u1 = x2[(size_t)s1 * 32 + lane];
            uint2 u2 = x2[(size_t)s2 * 32 + lane];
            uint2 u3 = x2[(size_t)s3 * 32 + lane];
            float2 a0 = __half22float2(*(__half2*)&u0.x), b0 = __half22float2(*(__half2*)&u0.y);
            float2 a1 = __half22float2(*(__half2*)&u1.x), b1 = __half22float2(*(__half2*)&u1.y);
            float2 a2 = __half22float2(*(__half2*)&u2.x), b2 = __half22float2(*(__half2*)&u2.y);
            float2 a3 = __half22float2(*(__half2*)&u3.x), b3 = __half22float2(*(__half2*)&u3.y);
            acc.x += w0 * a0.x + w1 * a1.x + w2 * a2.x + w3 * a3.x;
            acc.y += w0 * a0.y + w1 * a1.y + w2 * a2.y + w3 * a3.y;
            acc.z += w0 * b0.x + w1 * b1.x + w2 * b2.x + w3 * b3.x;
            acc.w += w0 * b0.y + w1 * b1.y + w2 * b2.y + w3 * b3.y;
        }
        for (; j < end; ++j) {
            int s0 = col[j];
            float w0 = dinv[s0];
            uint2 u0 = x2[(size_t)s0 * 32 + lane];
            float2 a0 = __half22float2(*(__half2*)&u0.x), b0 = __half22float2(*(__half2*)&u0.y);
            acc.x += w0 * a0.x; acc.y += w0 * a0.y;
            acc.z += w0 * b0.x; acc.w += w0 * b0.y;
        }
        acc.x *= dd; acc.y *= dd; acc.z *= dd; acc.w *= dd;
        float v[4] = { acc.x, acc.y, acc.z, acc.w };
        unsigned hh[2], ll[2];
        #pragma unroll
        for (int p = 0; p < 2; p++) {
            __nv_bfloat16 h0 = __float2bfloat16_rn(v[2 * p]);
            __nv_bfloat16 h1 = __float2bfloat16_rn(v[2 * p + 1]);
            __nv_bfloat16 l0 = __float2bfloat16_rn(v[2 * p] - __bfloat162float(h0));
            __nv_bfloat16 l1 = __float2bfloat16_rn(v[2 * p + 1] - __bfloat162float(h1));
            hh[p] = bf16_us(h0) | (bf16_us(h1) << 16);
            ll[p] = bf16_us(l0) | (bf16_us(l1) << 16);
        }
        size_t base = ((size_t)r * MPAD + node) * 128 + 4 * lane;
        *(uint2*)(g_agghi + base) = make_uint2(hh[0], hh[1]);
        *(uint2*)(g_agglo + base) = make_uint2(ll[0], ll[1]);
    }
}

// ---------------- tcgen05 split-bf16 GEMM -------------------------------------
// modes: 0: Hout(fp16) = relu(D)   1: H2 bf16 hi/lo + BN stats   2: fused lin2
#define SM_AHI 1024
#define SM_ALO (1024 + 32768)
#define SM_BHI (1024 + 65536)
#define SM_BLO (1024 + 98304)
#define SM_TOTAL (1024 + 131072)
#define SM_MBAR 8
#define SM_BIAS 16

__global__ void __launch_bounds__(256) mma_gemm(
    const __nv_bfloat16* __restrict__ Ahi, const __nv_bfloat16* __restrict__ Alo,
    const __nv_bfloat16* __restrict__ Bhi, const __nv_bfloat16* __restrict__ Blo,
    const float* __restrict__ bias, int nrel,
    __half* __restrict__ HoutH,
    __nv_bfloat16* __restrict__ H2hi, __nv_bfloat16* __restrict__ H2lo,
    const float* __restrict__ l2W, const float* __restrict__ l2b,
    float* __restrict__ out2, int mode)
{
    extern __shared__ char sm[];
    uint32_t smb = smem_to_u32(sm);
    int tid = threadIdx.x;
    int wid = tid >> 5;
    int rowBase = blockIdx.x * 128;

    if (wid == 0) TCGEN05_ALLOC(smb, 128);
    if (tid == 0) MBARRIER_INIT(smb + SM_MBAR, 1);
    if (tid < 128) {
        float s = 0.f;
        for (int r = 0; r < nrel; r++) s += bias[r * 128 + tid];
        *(float*)(sm + SM_BIAS + tid * 4) = s;
    }
    __syncthreads();
    uint32_t tmem;
    asm volatile("ld.shared.b32 %0, [%1];" : "=r"(tmem) : "r"(smb));

    for (int r = 0; r < nrel; ++r) {
        if (r) {
            MBARRIER_WAIT_PARITY(smb + SM_MBAR, (r - 1) & 1);
            __syncthreads();
        }
        for (int c = tid; c < 2048; c += 256) {
            int row = c >> 4;
            int kc  = c & 15;
            uint32_t soff = (uint32_t)(((row >> 3) + ((kc >> 3) << 4)) * 1024 + (row & 7) * 128 + (kc & 7) * 16);
            soff = soff ^ ((soff >> 3) & 0x70);
            size_t gA = ((size_t)r * MPAD + rowBase + row) * 128 + kc * 8;
            *(uint4*)(sm + SM_AHI + soff) = *(const uint4*)(Ahi + gA);
            *(uint4*)(sm + SM_ALO + soff) = *(const uint4*)(Alo + gA);
            size_t gB = ((size_t)r * 128 + row) * 128 + kc * 8;
            *(uint4*)(sm + SM_BHI + soff) = *(const uint4*)(Bhi + gB);
            *(uint4*)(sm + SM_BLO + soff) = *(const uint4*)(Blo + gB);
        }
        __syncthreads();
        if (wid == 0) {
            FENCE_PROXY_ASYNC();
            if (elect_one_pred()) {
                uint64_t aH = make_desc(smb + SM_AHI);
                uint64_t aL = make_desc(smb + SM_ALO);
                uint64_t bH = make_desc(smb + SM_BHI);
                uint64_t bL = make_desc(smb + SM_BLO);
                #pragma unroll
                for (int s = 0; s < 8; ++s) {
                    uint64_t off = (uint64_t)((s >> 2) * 1024 + (s & 3) * 2);
                    mma_f16_ss(tmem, aH + off, bH + off, MMA_IDESC, !(r == 0 && s == 0));
                    mma_f16_ss(tmem, aH + off, bL + off, MMA_IDESC, 1u);
                    mma_f16_ss(tmem, aL + off, bH + off, MMA_IDESC, 1u);
                }
                TCGEN05_COMMIT(smb + SM_MBAR);
            }
        }
    }

    MBARRIER_WAIT_PARITY(smb + SM_MBAR, (nrel - 1) & 1);
    TCGEN05_FENCE_AFTER();

    float* vs = (float*)(sm + SM_AHI);   // [128][129] BN scratch (mode 1)

    if (tid < 128) {
        int row = rowBase + tid;
        bool active = row < N_NODES;
        float p0 = 0.f, p1 = 0.f;
        for (int ch = 0; ch < 4; ++ch) {
            uint32_t regs[32];
            TCGEN05_LD_X32(regs, tmem + ch * 32);
            TCGEN05_WAIT_LD();
            float v[32];
            #pragma unroll
            for (int c = 0; c < 32; ++c) {
                float b = *(const float*)(sm + SM_BIAS + (ch * 32 + c) * 4);
                v[c] = active ? fmaxf(__uint_as_float(regs[c]) + b, 0.f) : 0.f;
            }
            if (mode == 0) {
                if (active) {
                    uint32_t pk[16];
                    #pragma unroll
                    for (int p = 0; p < 16; ++p) {
                        __half2 h = __floats2half2_rn(v[2 * p], v[2 * p + 1]);
                        pk[p] = *(uint32_t*)&h;
                    }
                    #pragma unroll
                    for (int g = 0; g < 4; ++g)
                        *(uint4*)(HoutH + (size_t)row * 128 + ch * 32 + g * 8) =
                            make_uint4(pk[4 * g], pk[4 * g + 1], pk[4 * g + 2], pk[4 * g + 3]);
                }
            } else if (mode == 1) {
                #pragma unroll
                for (int c = 0; c < 32; ++c) vs[tid * 129 + ch * 32 + c] = v[c];
                if (active) {
                    unsigned hh[16], ll[16];
                    #pragma unroll
                    for (int p = 0; p < 16; ++p) {
                        __nv_bfloat16 h0 = __float2bfloat16_rn(v[2 * p]);
                        __nv_bfloat16 h1 = __float2bfloat16_rn(v[2 * p + 1]);
                        __nv_bfloat16 l0 = __float2bfloat16_rn(v[2 * p] - __bfloat162float(h0));
                        __nv_bfloat16 l1 = __float2bfloat16_rn(v[2 * p + 1] - __bfloat162float(h1));
                        hh[p] = bf16_us(h0) | (bf16_us(h1) << 16);
                        ll[p] = bf16_us(l0) | (bf16_us(l1) << 16);
                    }
                    #pragma unroll
                    for (int g = 0; g < 4; ++g) {
                        *(uint4*)(H2hi + (size_t)row * 128 + ch * 32 + g * 8) =
                            make_uint4(hh[4 * g], hh[4 * g + 1], hh[4 * g + 2], hh[4 * g + 3]);
                        *(uint4*)(H2lo + (size_t)row * 128 + ch * 32 + g * 8) =
                            make_uint4(ll[4 * g], ll[4 * g + 1], ll[4 * g + 2], ll[4 * g + 3]);
                    }
                }
            } else {
                #pragma unroll
                for (int c = 0; c < 32; ++c) {
                    int col = ch * 32 + c;
                    p0 += v[c] * l2W[col * 2 + 0];
                    p1 += v[c] * l2W[col * 2 + 1];
                }
            }
        }
        if (mode == 2 && active) {
            out2[(size_t)row * 2 + 0] = p0 + l2b[0];
            out2[(size_t)row * 2 + 1] = p1 + l2b[1];
        }
    }
    __syncthreads();

    if (mode == 1) {
        int col = tid >> 1;
        int r0 = (tid & 1) * 64;
        float s = 0.f, ss = 0.f;
        #pragma unroll 8
        for (int rr = 0; rr < 64; ++rr) {
            float v = vs[(r0 + rr) * 129 + col];
            s += v; ss += v * v;
        }
        atomicAdd(&g_bnsum[col], s);
        atomicAdd(&g_bnsq[col], ss);
        __syncthreads();
    }

    if (tid == 0) MBARRIER_INVAL(smb + SM_MBAR);
    if (wid == 0) TCGEN05_DEALLOC(tmem, 128);
}

// ---------------- fold BN into lin1, emit bf16 hi/lo ---------------------------
__global__ void bn_fold_kernel(const float* __restrict__ gamma,
                               const float* __restrict__ beta,
                               const float* __restrict__ lin1W,
                               const float* __restrict__ lin1b)
{
    __shared__ float s_sc[128], s_sh[128];
    int j = threadIdx.x;
    float mean = g_bnsum[j] / (float)N_NODES;
    float var  = g_bnsq[j] / (float)N_NODES - mean * mean;
    float sc = gamma[j] * rsqrtf(var + BN_EPS);
    s_sc[j] = sc;
    s_sh[j] = beta[j] - mean * sc;
    __syncthreads();
    float bp = lin1b[j];
    for (int k = 0; k < 128; k++) {
        float w = lin1W[k * 128 + j];
        float wp = s_sc[k] * w;
        __nv_bfloat16 h = __float2bfloat16_rn(wp);
        g_Wphi[j * 128 + k] = h;
        g_Wplo[j * 128 + k] = __float2bfloat16_rn(wp - __bfloat162float(h));
        bp += s_sh[k] * w;
    }
    g_bp[j] = bp;
}

// ---------------- launch -------------------------------------------------------
extern "C" void kernel_launch(void* const* d_in, const int* in_sizes, int n_in,
                              void* d_out, int out_size)
{
    const float* x      = (const float*)d_in[0];
    const int*   ei     = (const int*)d_in[1];
    const float* W1     = (const float*)d_in[2];
    const float* b1     = (const float*)d_in[3];
    const float* W2     = (const float*)d_in[4];
    const float* b2     = (const float*)d_in[5];
    const float* gamma  = (const float*)d_in[6];
    const float* beta   = (const float*)d_in[7];
    const float* lin1W  = (const float*)d_in[8];
    const float* lin1b  = (const float*)d_in[9];
    const float* lin2W  = (const float*)d_in[10];
    const float* lin2b  = (const float*)d_in[11];
    float* out = (float*)d_out;

    cudaFuncSetAttribute(mma_gemm, cudaFuncAttributeMaxDynamicSharedMemorySize, SM_TOTAL);

    int* cnt;
    float* bp;
    __half *xh, *h1h;
    __nv_bfloat16 *agghi, *agglo, *B1hi, *B1lo, *B2hi, *B2lo, *Wphi, *Wplo, *h2hi, *h2lo;
    cudaGetSymbolAddress((void**)&cnt,    g_cnt);
    cudaGetSymbolAddress((void**)&bp,     g_bp);
    cudaGetSymbolAddress((void**)&xh,     g_xh);
    cudaGetSymbolAddress((void**)&h1h,    g_h1h);
    cudaGetSymbolAddress((void**)&agghi,  g_agghi);
    cudaGetSymbolAddress((void**)&agglo,  g_agglo);
    cudaGetSymbolAddress((void**)&B1hi,   g_B1hi);
    cudaGetSymbolAddress((void**)&B1lo,   g_B1lo);
    cudaGetSymbolAddress((void**)&B2hi,   g_B2hi);
    cudaGetSymbolAddress((void**)&B2lo,   g_B2lo);
    cudaGetSymbolAddress((void**)&Wphi,   g_Wphi);
    cudaGetSymbolAddress((void**)&Wplo,   g_Wplo);
    cudaGetSymbolAddress((void**)&h2hi,   g_h2hi);
    cudaGetSymbolAddress((void**)&h2lo,   g_h2lo);

    const int edge4Blocks = (N_EDGES / 4 + 255) / 256;   // 489
    const int aggBlocks   = (N_NODES + 7) / 8;           // 6250
    const int gemmBlocks  = MPAD / 128;                  // 391

    cudaMemsetAsync(cnt, 0, sizeof(int) * NREL * N_NODES);

    xconv_kernel<<<(N_NODES * HID / 4 + 255) / 256, 256>>>(x);
    count_kernel<<<dim3(edge4Blocks, NREL), 256>>>(ei);
    scanA_kernel<<<dim3(NBLK, NREL), 1024>>>();
    scan_fin_kernel<<<dim3(NBLK, NREL), 1024>>>();
    fill_kernel<<<dim3(edge4Blocks, NREL), 256>>>(ei);
    bprep_kernel<<<(NREL * HID * HID + 255) / 256, 256>>>(W1, W2);

    // layer 1: fp16 gather x -> split-bf16 MMA -> h1 (fp16)
    aggregate_kernel<<<aggBlocks, 256>>>(xh);
    mma_gemm<<<gemmBlocks, 256, SM_TOTAL>>>(agghi, agglo, B1hi, B1lo, b1, NREL,
                                            h1h, nullptr, nullptr,
                                            nullptr, nullptr, nullptr, 0);
    // layer 2: fp16 gather h1 -> split-bf16 MMA -> h2 hi/lo + BN stats
    aggregate_kernel<<<aggBlocks, 256>>>(h1h);
    mma_gemm<<<gemmBlocks, 256, SM_TOTAL>>>(agghi, agglo, B2hi, B2lo, b2, NREL,
                                            nullptr, h2hi, h2lo,
                                            nullptr, nullptr, nullptr, 1);
    // BN fold -> lin1 bf16 hi/lo; lin1 GEMM + fused lin2 epilogue -> out
    bn_fold_kernel<<<1, 128>>>(gamma, beta, lin1W, lin1b);
    mma_gemm<<<gemmBlocks, 256, SM_TOTAL>>>(h2hi, h2lo, Wphi, Wplo, bp, 1,
                                            nullptr, nullptr, nullptr,
                                            lin2W, lin2b, out, 2);
}